// round 12
// baseline (speedup 1.0000x reference)
#include <cuda_runtime.h>
#include <cuda_fp16.h>
#include <cstdint>

#define BATCH 64
#define T     4096
#define DIN   128
#define DST   256
#define DOUT  128

// ---------------------------------------------------------------------------
// PTX helpers (sm_90+ cluster / mbarrier / st.async)
// ---------------------------------------------------------------------------
__device__ __forceinline__ uint32_t ctarank() {
    uint32_t r; asm("mov.u32 %0, %%cluster_ctarank;" : "=r"(r)); return r;
}
__device__ __forceinline__ uint32_t smem_u32(const void* p) {
    uint32_t a;
    asm("{ .reg .u64 t; cvta.to.shared.u64 t, %1; cvt.u32.u64 %0, t; }"
        : "=r"(a) : "l"(p));
    return a;
}
__device__ __forceinline__ uint32_t mapa_u32(uint32_t l, uint32_t r) {
    uint32_t v; asm("mapa.shared::cluster.u32 %0, %1, %2;" : "=r"(v) : "r"(l), "r"(r));
    return v;
}
__device__ __forceinline__ void mbar_init(uint32_t m, uint32_t cnt) {
    asm volatile("mbarrier.init.shared.b64 [%0], %1;" :: "r"(m), "r"(cnt) : "memory");
}
__device__ __forceinline__ void mbar_expect(uint32_t m, uint32_t tx) {
    asm volatile("mbarrier.arrive.expect_tx.shared.b64 _, [%0], %1;"
                 :: "r"(m), "r"(tx) : "memory");
}
__device__ __forceinline__ void mbar_wait(uint32_t m, uint32_t parity) {
    asm volatile(
        "{\n\t.reg .pred P;\n\t"
        "W_%=:\n\t"
        "mbarrier.try_wait.parity.acquire.cluster.shared::cta.b64 P, [%0], %1, 0x989680;\n\t"
        "@!P bra W_%=;\n\t}"
        :: "r"(m), "r"(parity) : "memory");
}
__device__ __forceinline__ void st_async_b32(uint32_t raddr, uint32_t val, uint32_t rmbar) {
    asm volatile("st.async.shared::cluster.mbarrier::complete_tx::bytes.b32 [%0], %1, [%2];"
                 :: "r"(raddr), "r"(val), "r"(rmbar) : "memory");
}
#define CLUSTER_SYNC() do { \
    asm volatile("barrier.cluster.arrive.aligned;" ::: "memory"); \
    asm volatile("barrier.cluster.wait.aligned;"   ::: "memory"); \
} while (0)

// Exact identity tanh: 1 - 2/(1+e^{2s}).  |err| ~1e-6, branch-free.
__device__ __forceinline__ float tanh_fast(float s) {
    float e = __expf(2.0f * s);
    return 1.0f - __fdividef(2.0f, e + 1.0f);
}

// 64 HFMA2 over a 128-half2 vector chunk into 8 chains (8 adds/chain per call)
#define MAC16(ACC, W, XB) do {                                           \
    const uint4* xp_ = (const uint4*)(XB);                               \
    _Pragma("unroll")                                                    \
    for (int j_ = 0; j_ < 16; j_ += 2) {                                 \
        uint4 v0_ = xp_[j_], v1_ = xp_[j_ + 1];                          \
        (ACC)[0] = __hfma2((W)[4*j_+0], *(__half2*)&v0_.x, (ACC)[0]);    \
        (ACC)[1] = __hfma2((W)[4*j_+1], *(__half2*)&v0_.y, (ACC)[1]);    \
        (ACC)[2] = __hfma2((W)[4*j_+2], *(__half2*)&v0_.z, (ACC)[2]);    \
        (ACC)[3] = __hfma2((W)[4*j_+3], *(__half2*)&v0_.w, (ACC)[3]);    \
        (ACC)[4] = __hfma2((W)[4*j_+4], *(__half2*)&v1_.x, (ACC)[4]);    \
        (ACC)[5] = __hfma2((W)[4*j_+5], *(__half2*)&v1_.y, (ACC)[5]);    \
        (ACC)[6] = __hfma2((W)[4*j_+6], *(__half2*)&v1_.z, (ACC)[6]);    \
        (ACC)[7] = __hfma2((W)[4*j_+7], *(__half2*)&v1_.w, (ACC)[7]);    \
    } } while (0)

// 32 HFMA2 over a 32-half2 chunk into 8 chains (4 adds/chain per call)
#define MAC8(ACC, W, XB) do {                                            \
    const uint4* xp_ = (const uint4*)(XB);                               \
    _Pragma("unroll")                                                    \
    for (int j_ = 0; j_ < 8; j_ += 2) {                                  \
        uint4 v0_ = xp_[j_], v1_ = xp_[j_ + 1];                          \
        (ACC)[0] = __hfma2((W)[4*j_+0], *(__half2*)&v0_.x, (ACC)[0]);    \
        (ACC)[1] = __hfma2((W)[4*j_+1], *(__half2*)&v0_.y, (ACC)[1]);    \
        (ACC)[2] = __hfma2((W)[4*j_+2], *(__half2*)&v0_.z, (ACC)[2]);    \
        (ACC)[3] = __hfma2((W)[4*j_+3], *(__half2*)&v0_.w, (ACC)[3]);    \
        (ACC)[4] = __hfma2((W)[4*j_+4], *(__half2*)&v1_.x, (ACC)[4]);    \
        (ACC)[5] = __hfma2((W)[4*j_+5], *(__half2*)&v1_.y, (ACC)[5]);    \
        (ACC)[6] = __hfma2((W)[4*j_+6], *(__half2*)&v1_.z, (ACC)[6]);    \
        (ACC)[7] = __hfma2((W)[4*j_+7], *(__half2*)&v1_.w, (ACC)[7]);    \
    } } while (0)

__device__ __forceinline__ float hsum8a(const __half2* q) {
    float2 a0 = __half22float2(q[0]), a1 = __half22float2(q[1]);
    float2 a2 = __half22float2(q[2]), a3 = __half22float2(q[3]);
    float2 a4 = __half22float2(q[4]), a5 = __half22float2(q[5]);
    float2 a6 = __half22float2(q[6]), a7 = __half22float2(q[7]);
    return (((a0.x+a0.y)+(a1.x+a1.y)) + ((a2.x+a2.y)+(a3.x+a3.y)))
         + (((a4.x+a4.y)+(a5.x+a5.y)) + ((a6.x+a6.y)+(a7.x+a7.y)));
}

// ---------------------------------------------------------------------------
// Role-split fused SSM: 64 clusters of 2 CTAs (one per batch), 256 thr/CTA.
// CTA rank r owns states [r*128,+128) and outputs [r*64,+64).
// A-threads (tid<128): thread sl computes the FULL A row for state sg
//   (local 128-K chunk pre-wait, peer chunk post-wait), adds psB (B.u_t from
//   shared), tanh, publishes x_{t+1}: self half = plain STS (pre-barrier,
//   ordered for next step by the step barrier); peer half = st.async issued
//   at the START of the next step (formally after all reads of that buffer).
// C-threads: B.u_{t+1} (pre-wait, into psB[nxt]) + y half (local pre-wait,
//   peer post-wait); y stored with a 2-step lag via yps partner exchange.
// ONE __syncthreads per step.
// ---------------------------------------------------------------------------
__global__ void __launch_bounds__(256, 1) __cluster_dims__(2, 1, 1)
ssm_fused(const float* __restrict__ u, const float* __restrict__ A,
          const float* __restrict__ B, const float* __restrict__ C,
          float* __restrict__ out)
{
    __shared__ __align__(16) __half xs[2][DST];   // x_t (t&1 selects buffer)
    __shared__ __align__(16) __half us[2][DIN];   // u_{t+1} (parity)
    __shared__ float psB[2][128];                 // B.u_t per local state (parity)
    __shared__ float yps[2][64];                  // y partner partial (parity)
    __shared__ __align__(8) unsigned long long mb[2];

    const int tid = threadIdx.x;
    const bool isA = tid < 128;
    const int sl = tid & 127;                     // A: state; C: B-state index
    const int ct = sl;
    const int o  = ct & 63;                       // C: output index
    const int ch = (ct >> 6) & 1;                 // C: K-half selector
    const uint32_t rank = ctarank();
    const uint32_t peer = rank ^ 1u;
    const int b  = blockIdx.x >> 1;
    const int sg = ((int)rank << 7) + sl;

    const int AL = (int)rank << 7;                // A local K chunk (elements)
    const int AP = (int)peer << 7;                // A peer  K chunk
    const int YL = ((int)rank << 7) + (ch << 6);  // C local 64-state chunk
    const int YP = ((int)peer << 7) + (ch << 6);  // C peer  64-state chunk

    const uint32_t mb0 = smem_u32(&mb[0]), mb1 = smem_u32(&mb[1]);
    const uint32_t xs0 = smem_u32(&xs[0][0]), xs1 = smem_u32(&xs[1][0]);

    if (tid == 0) {
        mbar_init(mb0, 1); mbar_init(mb1, 1);
        mbar_expect(mb0, 256); mbar_expect(mb1, 256);   // peer half only: 256 B
    }
    if (tid < 128) ((uint32_t*)&xs[0][0])[tid] = 0u;     // x_0 = 0 (full 512 B)

    // Register weight tiles (fp32 -> fp16), one-time.
    //   A-threads: wA = A[sg][local 128K], wB = A[sg][peer 128K]
    //   C-threads: wA = B[rank*128+ct][0..128), wB = {C local 32, C peer 32}
    __half2 wA[64], wB[64];
    if (isA) {
        const float* Ar = A + (size_t)sg * DST;
        const float2* Al = (const float2*)(Ar + AL);
        const float2* Ap = (const float2*)(Ar + AP);
#pragma unroll
        for (int j = 0; j < 64; j++) { float2 v = Al[j]; wA[j] = __floats2half2_rn(v.x, v.y); }
#pragma unroll
        for (int j = 0; j < 64; j++) { float2 v = Ap[j]; wB[j] = __floats2half2_rn(v.x, v.y); }
    } else {
        const float2* Br = (const float2*)(B + (size_t)(((int)rank << 7) + ct) * DIN);
#pragma unroll
        for (int j = 0; j < 64; j++) { float2 v = Br[j]; wA[j] = __floats2half2_rn(v.x, v.y); }
        const float* Cr = C + (size_t)(((int)rank << 6) + o) * DST;
        const float2* Cl = (const float2*)(Cr + YL);
        const float2* Cp = (const float2*)(Cr + YP);
#pragma unroll
        for (int j = 0; j < 32; j++) { float2 v = Cl[j]; wB[j]      = __floats2half2_rn(v.x, v.y); }
#pragma unroll
        for (int j = 0; j < 32; j++) { float2 v = Cp[j]; wB[32 + j] = __floats2half2_rn(v.x, v.y); }
    }

    const size_t urow = (size_t)b * T;
    const __half2 z = __float2half2_rn(0.f);
    __half2 q[8], r[8];

    // Pre-loop: psB[0] = B . u_0 ; us[0] = u_1 ; un = u_2
    if (tid < 128) us[0][tid] = __float2half(u[urow * DIN + tid]);      // u_0 (staged)
    __syncthreads();
    if (!isA) {
#pragma unroll
        for (int i = 0; i < 8; i++) r[i] = z;
        MAC16(r, wA, &us[0][0]);
        psB[0][ct] = hsum8a(r);
    }
    __syncthreads();                                                     // protect us[0]
    if (tid < 128) us[0][tid] = __float2half(u[(urow + 1) * DIN + tid]); // u_1
    float un = isA ? u[(urow + 2) * DIN + sl] : 0.f;                     // u_2
    __syncthreads();     // local init visible
    CLUSTER_SYNC();      // peer mbarriers armed before any st.async

    const uint32_t rx[2] = { mapa_u32(xs0, peer), mapa_u32(xs1, peer) };
    const uint32_t rm[2] = { mapa_u32(mb0, peer), mapa_u32(mb1, peer) };

    int ph0 = 0, ph1 = 0;
    uint32_t pk = 0;          // packed pair of x (even-A lanes)
    float fy_prev = 0.f;      // C ch1: saved y partial
    float* outb = out + urow * DOUT + ((int)rank << 6) + o;

#pragma unroll 1
    for (int t = 0; t < T; ++t) {
        const int cur = t & 1, nxt = cur ^ 1;
        const __half* xc = xs[cur];

        // ---------------- pre-wait region ----------------
        if (isA) {
            // Ship x_t peer half NOW (issued after last step's barrier, so it
            // is ordered after every read of xs[cur] on both CTAs).
            if (t > 0 && !(sl & 1))
                st_async_b32(rx[cur] + (uint32_t)(sg << 1), pk, rm[cur]);
#pragma unroll
            for (int i = 0; i < 8; i++) q[i] = z;
            MAC16(q, wA, xc + AL);                       // local A chunk
            us[nxt][sl] = __float2half(un);              // publish u_{t+2}
            un = (t + 3 < T) ? u[(urow + t + 3) * DIN + sl] : 0.f;
        } else {
#pragma unroll
            for (int i = 0; i < 8; i++) { q[i] = z; r[i] = z; }
            MAC16(r, wA, &us[cur][0]);                   // B . u_{t+1}
            psB[nxt][ct] = hsum8a(r);
            MAC8(q, wB, xc + YL);                        // local y chunk
            if (ch && t >= 2)                            // y_{t-2} store (lagged)
                outb[(size_t)(t - 2) * DOUT] = fy_prev + yps[nxt][o];
        }

        // ---------------- wait for peer half of x_t ----------------
        if (t > 0) {
            if (cur == 0) { mbar_wait(mb0, ph0); ph0 ^= 1; if (tid == 0) mbar_expect(mb0, 256); }
            else          { mbar_wait(mb1, ph1); ph1 ^= 1; if (tid == 0) mbar_expect(mb1, 256); }
        }

        // ---------------- post-wait region ----------------
        if (isA) {
            MAC16(q, wB, xc + AP);                       // peer A chunk
            const float s  = hsum8a(q) + psB[cur][sl];   // + B.u_t
            const float xv = tanh_fast(s);
            const unsigned hv = (unsigned)__half_as_ushort(__float2half_rn(xv));
            const unsigned nb = __shfl_down_sync(0xffffffffu, hv, 1);
            if (!(sl & 1)) {
                pk = hv | (nb << 16);
                *((uint32_t*)&xs[nxt][sg]) = pk;         // self half: plain STS
            }
        } else {
            MAC8(q, wB + 32, xc + YP);                   // peer y chunk
            const float fy = hsum8a(q);                  // half of y_{t-1}
            if (ch == 0) yps[cur][o] = fy; else fy_prev = fy;
        }
        __syncthreads();                                 // the ONLY per-step barrier
    }

    // Epilogue: ship x_T peer half, then y_{T-2} (pending) and y_{T-1}.
    if (isA && !(sl & 1))
        st_async_b32(rx[0] + (uint32_t)(sg << 1), pk, rm[0]);
    mbar_wait(mb0, ph0);
    if (!isA) {
        if (ch) outb[(size_t)(T - 2) * DOUT] = fy_prev + yps[1][o];
#pragma unroll
        for (int i = 0; i < 8; i++) q[i] = z;
        MAC8(q, wB,      xs[0] + YL);
        MAC8(q, wB + 32, xs[0] + YP);
        const float fy = hsum8a(q);
        if (ch == 0) yps[0][o] = fy; else fy_prev = fy;
    }
    __syncthreads();
    if (!isA && ch)
        outb[(size_t)(T - 1) * DOUT] = fy_prev + yps[0][o];
    CLUSTER_SYNC();                                      // no early exit under peer traffic
}

// ---------------------------------------------------------------------------
// Single launch: 128 CTAs = 64 two-CTA clusters, one wave on 148 SMs.
// ---------------------------------------------------------------------------
extern "C" void kernel_launch(void* const* d_in, const int* in_sizes, int n_in,
                              void* d_out, int out_size) {
    const float* u = (const float*)d_in[0];   // [64,4096,128]
    const float* A = (const float*)d_in[1];   // [256,256]
    const float* B = (const float*)d_in[2];   // [256,128]
    const float* C = (const float*)d_in[3];   // [128,256]
    float* out = (float*)d_out;               // [64,4096,128]

    ssm_fused<<<BATCH * 2, 256>>>(u, A, B, C, out);
}

// round 13
// speedup vs baseline: 1.0434x; 1.0434x over previous
#include <cuda_runtime.h>
#include <cuda_fp16.h>
#include <cstdint>

#define BATCH 64
#define T     4096
#define DIN   128
#define DST   256
#define DOUT  128

// ---------------------------------------------------------------------------
// PTX helpers (sm_90+ cluster / mbarrier / st.async)
// ---------------------------------------------------------------------------
__device__ __forceinline__ uint32_t ctarank() {
    uint32_t r; asm("mov.u32 %0, %%cluster_ctarank;" : "=r"(r)); return r;
}
__device__ __forceinline__ uint32_t smem_u32(const void* p) {
    uint32_t a;
    asm("{ .reg .u64 t; cvta.to.shared.u64 t, %1; cvt.u32.u64 %0, t; }"
        : "=r"(a) : "l"(p));
    return a;
}
__device__ __forceinline__ uint32_t mapa_u32(uint32_t l, uint32_t r) {
    uint32_t v; asm("mapa.shared::cluster.u32 %0, %1, %2;" : "=r"(v) : "r"(l), "r"(r));
    return v;
}
__device__ __forceinline__ void mbar_init(uint32_t m, uint32_t cnt) {
    asm volatile("mbarrier.init.shared.b64 [%0], %1;" :: "r"(m), "r"(cnt) : "memory");
}
__device__ __forceinline__ void mbar_expect(uint32_t m, uint32_t tx) {
    asm volatile("mbarrier.arrive.expect_tx.shared.b64 _, [%0], %1;"
                 :: "r"(m), "r"(tx) : "memory");
}
__device__ __forceinline__ void mbar_wait(uint32_t m, uint32_t parity) {
    asm volatile(
        "{\n\t.reg .pred P;\n\t"
        "W_%=:\n\t"
        "mbarrier.try_wait.parity.acquire.cluster.shared::cta.b64 P, [%0], %1, 0x989680;\n\t"
        "@!P bra W_%=;\n\t}"
        :: "r"(m), "r"(parity) : "memory");
}
__device__ __forceinline__ void st_async_b32(uint32_t raddr, uint32_t val, uint32_t rmbar) {
    asm volatile("st.async.shared::cluster.mbarrier::complete_tx::bytes.b32 [%0], %1, [%2];"
                 :: "r"(raddr), "r"(val), "r"(rmbar) : "memory");
}
#define CLUSTER_SYNC() do { \
    asm volatile("barrier.cluster.arrive.aligned;" ::: "memory"); \
    asm volatile("barrier.cluster.wait.aligned;"   ::: "memory"); \
} while (0)

// Exact identity tanh: 1 - 2/(1+e^{2s}).  |err| ~1e-6 (validated in R11).
__device__ __forceinline__ float tanh_fast(float s) {
    float e = __expf(2.0f * s);
    return 1.0f - __fdividef(2.0f, e + 1.0f);
}

// 64 HFMA2 over a 128-half (16 uint4) region into 8 chains (8 adds/chain)
#define MAC64(ACC, W, XB) do {                                           \
    const uint4* xp_ = (const uint4*)(XB);                               \
    _Pragma("unroll")                                                    \
    for (int j_ = 0; j_ < 16; j_ += 2) {                                 \
        uint4 v0_ = xp_[j_], v1_ = xp_[j_ + 1];                          \
        (ACC)[0] = __hfma2((W)[4*j_+0], *(__half2*)&v0_.x, (ACC)[0]);    \
        (ACC)[1] = __hfma2((W)[4*j_+1], *(__half2*)&v0_.y, (ACC)[1]);    \
        (ACC)[2] = __hfma2((W)[4*j_+2], *(__half2*)&v0_.z, (ACC)[2]);    \
        (ACC)[3] = __hfma2((W)[4*j_+3], *(__half2*)&v0_.w, (ACC)[3]);    \
        (ACC)[4] = __hfma2((W)[4*j_+4], *(__half2*)&v1_.x, (ACC)[4]);    \
        (ACC)[5] = __hfma2((W)[4*j_+5], *(__half2*)&v1_.y, (ACC)[5]);    \
        (ACC)[6] = __hfma2((W)[4*j_+6], *(__half2*)&v1_.z, (ACC)[6]);    \
        (ACC)[7] = __hfma2((W)[4*j_+7], *(__half2*)&v1_.w, (ACC)[7]);    \
    } } while (0)

__device__ __forceinline__ float hsum8a(const __half2* q) {
    float2 a0 = __half22float2(q[0]), a1 = __half22float2(q[1]);
    float2 a2 = __half22float2(q[2]), a3 = __half22float2(q[3]);
    float2 a4 = __half22float2(q[4]), a5 = __half22float2(q[5]);
    float2 a6 = __half22float2(q[6]), a7 = __half22float2(q[7]);
    return (((a0.x+a0.y)+(a1.x+a1.y)) + ((a2.x+a2.y)+(a3.x+a3.y)))
         + (((a4.x+a4.y)+(a5.x+a5.y)) + ((a6.x+a6.y)+(a7.x+a7.y)));
}

// ---------------------------------------------------------------------------
// Partial-exchange fused SSM. 64 clusters x 2 CTAs; CTA r owns x-half
// K_r = states [r*128,+128) and outputs [r*64,+64). x NEVER crosses CTAs:
// each CTA computes A[s,K_r].x[K_r] for ALL 256 states from its local half
// and ships the 128 fp32 partials for the peer's states (512 B). tanh and
// the x publish are CTA-local (STS + one __syncthreads). y via the same
// partial trick, shipped one step lagged (256 B) on the same mbarrier.
//   W03 (warps 0-3, thread i): B.u_t (64 HFMA2) + A-own partial (64 HFMA2),
//     post-wait: tanh(pOwn + recv + bU) -> STS xo[nxt].
//   W47 (warps 4-7, thread i): A-peer partial (64) -> ship ASAP (hi-wid
//     priority), then C partial for output i (64); post-wait: y store.
// ---------------------------------------------------------------------------
__global__ void __launch_bounds__(256, 1) __cluster_dims__(2, 1, 1)
ssm_fused(const float* __restrict__ u, const float* __restrict__ A,
          const float* __restrict__ B, const float* __restrict__ C,
          float* __restrict__ out)
{
    __shared__ __align__(16) __half xo[2][128];   // own x half (parity t&1)
    __shared__ __align__(16) __half us[2][128];   // u_t staging (parity)
    __shared__ float pA[2][128];                  // received A-partials (own states)
    __shared__ float pC[2][64];                   // received C-partials (own outputs)
    __shared__ __align__(8) unsigned long long mb[2];

    const int tid = threadIdx.x;
    const bool W47 = tid >= 128;
    const int i = tid & 127;
    const uint32_t rank = ctarank();
    const uint32_t peer = rank ^ 1u;
    const int b = blockIdx.x >> 1;
    const int kcol = (int)rank << 7;              // local K-half column offset
    const bool own_o = W47 && ((i >> 6) == (int)rank);   // warp-uniform
    const int oloc = i & 63;

    const uint32_t mb0 = smem_u32(&mb[0]), mb1 = smem_u32(&mb[1]);

    if (tid == 0) {
        mbar_init(mb0, 1); mbar_init(mb1, 1);
        mbar_expect(mb0, 768); mbar_expect(mb1, 768);  // 512 B A + 256 B C
    }
    if (tid < 64) ((uint32_t*)&xo[0][0])[tid] = 0u;    // x_0 = 0 (own half)

    // Register weight tiles (fp32 -> fp16), one-time.
    //  W03: wX = A[rank*128+i][K_r], wY = B[rank*128+i][0:128)
    //  W47: wX = A[peer*128+i][K_r], wY = C[i][K_r]
    __half2 wX[64], wY[64];
    if (!W47) {
        const int s = ((int)rank << 7) + i;
        const float2* Ar = (const float2*)(A + (size_t)s * DST + kcol);
        const float2* Br = (const float2*)(B + (size_t)s * DIN);
#pragma unroll
        for (int j = 0; j < 64; j++) { float2 v = Ar[j]; wX[j] = __floats2half2_rn(v.x, v.y); }
#pragma unroll
        for (int j = 0; j < 64; j++) { float2 v = Br[j]; wY[j] = __floats2half2_rn(v.x, v.y); }
    } else {
        const int s = ((int)peer << 7) + i;
        const float2* Ar = (const float2*)(A + (size_t)s * DST + kcol);
        const float2* Cr = (const float2*)(C + (size_t)i * DST + kcol);
#pragma unroll
        for (int j = 0; j < 64; j++) { float2 v = Ar[j]; wX[j] = __floats2half2_rn(v.x, v.y); }
#pragma unroll
        for (int j = 0; j < 64; j++) { float2 v = Cr[j]; wY[j] = __floats2half2_rn(v.x, v.y); }
    }

    const size_t urow = (size_t)b * T;
    if (!W47) us[0][i] = __float2half(u[urow * DIN + i]);           // u_0
    float un = (!W47) ? u[(urow + 1) * DIN + i] : 0.f;              // u_1

    __syncthreads();     // xo[0], us[0] visible
    CLUSTER_SYNC();      // peer mbarriers armed before any st.async

    const uint32_t rpA[2] = { mapa_u32(smem_u32(&pA[0][0]), peer),
                              mapa_u32(smem_u32(&pA[1][0]), peer) };
    const uint32_t rpC[2] = { mapa_u32(smem_u32(&pC[0][0]), peer),
                              mapa_u32(smem_u32(&pC[1][0]), peer) };
    const uint32_t rmb[2] = { mapa_u32(mb0, peer), mapa_u32(mb1, peer) };

    const __half2 z = __float2half2_rn(0.f);
    __half2 q[8];
    int ph0 = 0, ph1 = 0;
    float shipC = 0.f;     // W47 peer-o: C partial of x_{t-1} (to ship)
    float yC_prev = 0.f;   // W47 own-o: local C partial of x_{t-1}
    float pship = 0.f;     // W47: last A partial (epilogue dummy)
    float fyc = 0.f;       // W47: C partial of x_t
    float* outb = out + urow * DOUT + i;   // valid for W47 own-o threads

#pragma unroll 1
    for (int t = 0; t < T; ++t) {
        const int cur = t & 1, nxt = cur ^ 1;
        const __half* xc = xo[cur];

        if (W47) {
            // Ship C partial of x_{t-1} immediately (value held from last iter)
            if (!own_o) st_async_b32(rpC[cur] + (uint32_t)(oloc << 2),
                                     __float_as_uint(shipC), rmb[cur]);
            // A-peer partial over local x half; ship ASAP (hi-wid priority)
#pragma unroll
            for (int k = 0; k < 8; k++) q[k] = z;
            MAC64(q, wX, xc);
            pship = hsum8a(q);
            st_async_b32(rpA[cur] + (uint32_t)(i << 2),
                         __float_as_uint(pship), rmb[cur]);
            // C partial for output i over local x half (x_t)
#pragma unroll
            for (int k = 0; k < 8; k++) q[k] = z;
            MAC64(q, wY, xc);
            fyc = hsum8a(q);
        } else {
            // B.u_t (x-independent)
#pragma unroll
            for (int k = 0; k < 8; k++) q[k] = z;
            MAC64(q, wY, &us[cur][0]);
            const float bU = hsum8a(q);
            // A-own partial over local x half
#pragma unroll
            for (int k = 0; k < 8; k++) q[k] = z;
            MAC64(q, wX, xc);
            const float pOwn = hsum8a(q);
            // stage u_{t+1}, prefetch u_{t+2}
            us[nxt][i] = __float2half(un);
            un = (t + 2 < T) ? u[(urow + t + 2) * DIN + i] : 0.f;
            // stash for post-wait (keep in regs across the wait)
            q[0] = __floats2half2_rn(0.f, 0.f);     // (no-op; keeps q live)
            // wait handled below; tanh after release
            // save scalars:
            fyc = pOwn;        // reuse fyc slot as pOwn carrier for W03
            shipC = bU;        // reuse shipC slot as bU carrier for W03
        }

        // Wait for peer partials of this step (A 512 B + lagged C 256 B)
        if (cur == 0) { mbar_wait(mb0, ph0); ph0 ^= 1; if (tid == 0) mbar_expect(mb0, 768); }
        else          { mbar_wait(mb1, ph1); ph1 ^= 1; if (tid == 0) mbar_expect(mb1, 768); }

        if (!W47) {
            // x_{t+1}[own i] = tanh(pOwn + recv + bU); publish locally
            const float xv = tanh_fast(fyc + pA[cur][i] + shipC);
            const unsigned hv = (unsigned)__half_as_ushort(__float2half_rn(xv));
            const unsigned nb = __shfl_down_sync(0xffffffffu, hv, 1);
            if (!(i & 1))
                ((uint32_t*)&xo[nxt][0])[i >> 1] = hv | (nb << 16);
        } else {
            if (own_o) {
                if (t >= 2) outb[(size_t)(t - 2) * DOUT] = yC_prev + pC[cur][oloc];
                yC_prev = fyc;
            } else {
                shipC = fyc;
            }
        }
        __syncthreads();    // xo[nxt] visible; pA/pC[cur] reads done before reuse
    }

    // Epilogue phase E0 (parity buffer 0): ship C partials of x_{T-1}
    // (+ dummy A 512 B to satisfy the armed 768-B expect), combine y[T-2].
    if (W47) {
        if (!own_o) st_async_b32(rpC[0] + (uint32_t)(oloc << 2),
                                 __float_as_uint(shipC), rmb[0]);
        st_async_b32(rpA[0] + (uint32_t)(i << 2), __float_as_uint(pship), rmb[0]);
    }
    mbar_wait(mb0, ph0);
    if (own_o) outb[(size_t)(T - 2) * DOUT] = yC_prev + pC[0][oloc];
    __syncthreads();

    // Epilogue phase E1 (buffer 1): C partials of x_T (= xo[0]), y[T-1].
    float fyT = 0.f;
    if (W47) {
#pragma unroll
        for (int k = 0; k < 8; k++) q[k] = z;
        MAC64(q, wY, xo[0]);
        fyT = hsum8a(q);
        if (!own_o) st_async_b32(rpC[1] + (uint32_t)(oloc << 2),
                                 __float_as_uint(fyT), rmb[1]);
        st_async_b32(rpA[1] + (uint32_t)(i << 2), __float_as_uint(pship), rmb[1]);
    }
    mbar_wait(mb1, ph1);
    if (own_o) outb[(size_t)(T - 1) * DOUT] = fyT + pC[1][oloc];
    CLUSTER_SYNC();                                // no early exit under peer traffic
}

// ---------------------------------------------------------------------------
// Single launch: 128 CTAs = 64 two-CTA clusters, one wave on 148 SMs.
// ---------------------------------------------------------------------------
extern "C" void kernel_launch(void* const* d_in, const int* in_sizes, int n_in,
                              void* d_out, int out_size) {
    const float* u = (const float*)d_in[0];   // [64,4096,128]
    const float* A = (const float*)d_in[1];   // [256,256]
    const float* B = (const float*)d_in[2];   // [256,128]
    const float* C = (const float*)d_in[3];   // [128,256]
    float* out = (float*)d_out;               // [64,4096,128]

    ssm_fused<<<BATCH * 2, 256>>>(u, A, B, C, out);
}